// round 6
// baseline (speedup 1.0000x reference)
#include <cuda_runtime.h>

#define F 128
#define CAP_N 51200
#define CAP_E 650000

// Scratch (no cudaMalloc allowed). float4 type guarantees 16B alignment.
__device__ float4 g_agg4[(size_t)CAP_N * (F / 4)];  // raw weighted sums S
__device__ float  g_denom[CAP_N];                   // softmax denominators

// ---------------------------------------------------------------------------
// packed f32x2 helpers (Blackwell FFMA2 — PTX-only, 2x fp32 FMA throughput)
// ---------------------------------------------------------------------------
__device__ __forceinline__ void ffma2(unsigned long long& d,
                                      unsigned long long a,
                                      unsigned long long b) {
    asm("fma.rn.f32x2 %0, %1, %2, %0;" : "+l"(d) : "l"(a), "l"(b));
}
__device__ __forceinline__ float hadd2(unsigned long long v) {
    float lo, hi;
    asm("mov.b64 {%0, %1}, %2;" : "=f"(lo), "=f"(hi) : "l"(v));
    return lo + hi;
}

// ---------------------------------------------------------------------------
// K0: zero scratch (graph memset nodes can't target __device__ globals)
// ---------------------------------------------------------------------------
__global__ void k_zero(int N) {
    int i = blockIdx.x * blockDim.x + threadIdx.x;
    int total4 = N * (F / 4);
    if (i < total4)
        g_agg4[i] = make_float4(0.f, 0.f, 0.f, 0.f);
    if (i < N)
        g_denom[i] = 0.f;
}

// ---------------------------------------------------------------------------
// K1: merged edge pass (softmax div deferred — it cancels in the L2 norm):
//     denom[t] += exp(w[e]);  S[t][:] += exp(w[e]) * x[src][:]
// one warp per edge, vector REDG per lane.
// ---------------------------------------------------------------------------
__global__ void k_edge(const float* __restrict__ x,
                       const int* __restrict__ ei,
                       const float* __restrict__ w, int E, int N) {
    int gid = blockIdx.x * blockDim.x + threadIdx.x;
    int e = gid >> 5;
    int lane = gid & 31;
    if (e >= E) return;
    int s = ei[e];
    int t = ei[E + e];
    if ((unsigned)s >= (unsigned)N || (unsigned)t >= (unsigned)N) return;
    float ew = expf(w[e]);
    if (lane == 0) atomicAdd(&g_denom[t], ew);
    float4 xv = reinterpret_cast<const float4*>(x)[(size_t)s * 32 + lane];
    float4 v = make_float4(ew * xv.x, ew * xv.y, ew * xv.z, ew * xv.w);
    atomicAdd(&g_agg4[(size_t)t * 32 + lane], v);
}

// ---------------------------------------------------------------------------
// K2 helper: one GEMM pass with k-paired FFMA2.
// WS: smem W pairs. One k2-row = 128 float2 = 64 ulonglong2 (stride 64!).
// xr[i]: row base pointers (ulonglong2, 16B chunks over k).
// acc[i][f]: f32x2 accumulators (even/odd k partial sums).
// ---------------------------------------------------------------------------
__device__ __forceinline__ void gemm_pass(const ulonglong2* __restrict__ WS,
                                          const ulonglong2* const* xr,
                                          unsigned long long (*acc)[4],
                                          int lane) {
    #pragma unroll 2
    for (int c = 0; c < 32; ++c) {          // chunk = 4 k = 2 k2 rows
        const ulonglong2* r0 = WS + (size_t)(2 * c) * 64;       // k2 = 2c
        const ulonglong2* r1 = WS + (size_t)(2 * c + 1) * 64;   // k2 = 2c+1
        ulonglong2 w0a = r0[2 * lane];
        ulonglong2 w0b = r0[2 * lane + 1];
        ulonglong2 w1a = r1[2 * lane];
        ulonglong2 w1b = r1[2 * lane + 1];
        #pragma unroll
        for (int i = 0; i < 8; ++i) {
            ulonglong2 xv = xr[i][c];       // (k 4c..4c+1, k 4c+2..4c+3)
            ffma2(acc[i][0], xv.x, w0a.x);
            ffma2(acc[i][1], xv.x, w0a.y);
            ffma2(acc[i][2], xv.x, w0b.x);
            ffma2(acc[i][3], xv.x, w0b.y);
            ffma2(acc[i][0], xv.y, w1a.x);
            ffma2(acc[i][1], xv.y, w1a.y);
            ffma2(acc[i][2], xv.y, w1b.x);
            ffma2(acc[i][3], xv.y, w1b.y);
        }
    }
}

// ---------------------------------------------------------------------------
// K2: fused dual GEMM (FFMA2) -> deferred softmax-div+L2-norm -> proj-avg -> LN
// 512 threads (16 warps), 128 nodes/block, 8 rows/warp, 4 out-feats/lane.
// smem: W_self pairs 64KB | W_nb pairs 64KB | self-result buffer 64KB = 192KB.
// ---------------------------------------------------------------------------
__global__ __launch_bounds__(512, 1)
void k_fused(const float* __restrict__ x,
             const float* __restrict__ Wself, const float* __restrict__ bself,
             const float* __restrict__ Wnb, const float* __restrict__ bnb,
             const float* __restrict__ gamma, const float* __restrict__ beta,
             float* __restrict__ out, int N) {
    extern __shared__ float sm[];
    float* WpS = sm;            // [64 k2][128 f] float2 (k-paired W_self)
    float* WpN = sm + 16384;    // same for W_nb
    float* Sb  = sm + 32768;    // [128 rows][128 f] self-pass result

    int tid = threadIdx.x;
    int base = blockIdx.x * 128;

    // stage W matrices into k-paired layout: Wp[k2][f] = (W[2k2][f], W[2k2+1][f])
    {
        const float4* gS = (const float4*)Wself;
        const float4* gN = (const float4*)Wnb;
        #pragma unroll
        for (int it = 0; it < 4; ++it) {
            int t4 = tid + it * 512;        // [0,2048)
            int k2 = t4 >> 5, g = t4 & 31;
            float4 a = gS[(2 * k2) * 32 + g];
            float4 b = gS[(2 * k2 + 1) * 32 + g];
            float2* d = (float2*)(WpS + k2 * 256) + g * 4;
            d[0] = make_float2(a.x, b.x);
            d[1] = make_float2(a.y, b.y);
            d[2] = make_float2(a.z, b.z);
            d[3] = make_float2(a.w, b.w);
            a = gN[(2 * k2) * 32 + g];
            b = gN[(2 * k2 + 1) * 32 + g];
            d = (float2*)(WpN + k2 * 256) + g * 4;
            d[0] = make_float2(a.x, b.x);
            d[1] = make_float2(a.y, b.y);
            d[2] = make_float2(a.z, b.z);
            d[3] = make_float2(a.w, b.w);
        }
    }
    __syncthreads();

    int warp = tid >> 5, lane = tid & 31;
    int rbase = warp * 8;

    // row pointers (clamped; out-of-range rows computed but never written)
    const ulonglong2* xr[8];
    const ulonglong2* ar[8];
    int nodes[8];
    #pragma unroll
    for (int i = 0; i < 8; ++i) {
        int node = base + rbase + i;
        nodes[i] = node;
        int nd = node < N ? node : 0;
        xr[i] = (const ulonglong2*)(x + (size_t)nd * F);
        ar[i] = (const ulonglong2*)(g_agg4 + (size_t)nd * 32);
    }

    unsigned long long acc[8][4];

    // ---- pass 1: self_feat = x @ W_self ----
    #pragma unroll
    for (int i = 0; i < 8; ++i)
        #pragma unroll
        for (int f = 0; f < 4; ++f) acc[i][f] = 0ULL;
    gemm_pass((const ulonglong2*)WpS, xr, acc, lane);
    #pragma unroll
    for (int i = 0; i < 8; ++i) {
        float4 sv;
        sv.x = hadd2(acc[i][0]);
        sv.y = hadd2(acc[i][1]);
        sv.z = hadd2(acc[i][2]);
        sv.w = hadd2(acc[i][3]);
        ((float4*)Sb)[(rbase + i) * 32 + lane] = sv;   // warp-private rows
    }

    // ---- deferred normalization scalars: inv = 1/(||S|| + denom*1e-9) ----
    float inv8[8];
    #pragma unroll
    for (int i = 0; i < 8; ++i) {
        int nd = nodes[i] < N ? nodes[i] : 0;
        float4 a = g_agg4[(size_t)nd * 32 + lane];
        float ss = a.x * a.x + a.y * a.y + a.z * a.z + a.w * a.w;
        #pragma unroll
        for (int off = 16; off; off >>= 1)
            ss += __shfl_xor_sync(0xffffffffu, ss, off);
        float dnm = g_denom[nd];
        inv8[i] = (ss > 0.f) ? 1.0f / (sqrtf(ss) + dnm * 1e-9f) : 0.f;
    }

    // ---- pass 2: nb_feat_raw = S @ W_nb ----
    #pragma unroll
    for (int i = 0; i < 8; ++i)
        #pragma unroll
        for (int f = 0; f < 4; ++f) acc[i][f] = 0ULL;
    gemm_pass((const ulonglong2*)WpN, ar, acc, lane);

    float4 bs = ((const float4*)bself)[lane];
    float4 bn = ((const float4*)bnb)[lane];
    float4 gm = ((const float4*)gamma)[lane];
    float4 bt = ((const float4*)beta)[lane];

    // ---- epilogue: combine -> proj-norm + LayerNorm -> store ----
    #pragma unroll
    for (int i = 0; i < 8; ++i) {
        if (nodes[i] >= N) continue;   // uniform per-warp tail
        float4 sv = ((const float4*)Sb)[(rbase + i) * 32 + lane];
        float iv = inv8[i];
        float4 c;
        c.x = 0.5f * ((sv.x + bs.x) + (iv * hadd2(acc[i][0]) + bn.x));
        c.y = 0.5f * ((sv.y + bs.y) + (iv * hadd2(acc[i][1]) + bn.y));
        c.z = 0.5f * ((sv.z + bs.z) + (iv * hadd2(acc[i][2]) + bn.z));
        c.w = 0.5f * ((sv.w + bs.w) + (iv * hadd2(acc[i][3]) + bn.w));
        float s1 = c.x + c.y + c.z + c.w;
        float s2 = c.x * c.x + c.y * c.y + c.z * c.z + c.w * c.w;
        #pragma unroll
        for (int off = 16; off; off >>= 1) {
            s1 += __shfl_xor_sync(0xffffffffu, s1, off);
            s2 += __shfl_xor_sync(0xffffffffu, s2, off);
        }
        float d = sqrtf(s2) + 1e-9f;
        float invd = 1.0f / d;
        float mean = s1 * invd * (1.0f / 128.0f);
        float e2 = s2 * invd * invd * (1.0f / 128.0f);
        float var = e2 - mean * mean;
        float isd = rsqrtf(var + 1e-5f);
        float4 o;
        o.x = (c.x * invd - mean) * isd * gm.x + bt.x;
        o.y = (c.y * invd - mean) * isd * gm.y + bt.y;
        o.z = (c.z * invd - mean) * isd * gm.z + bt.z;
        o.w = (c.w * invd - mean) * isd * gm.w + bt.w;
        ((float4*)out)[(size_t)nodes[i] * 32 + lane] = o;
    }
}

// ---------------------------------------------------------------------------
extern "C" void kernel_launch(void* const* d_in, const int* in_sizes, int n_in,
                              void* d_out, int out_size) {
    const float* x     = (const float*)d_in[0];
    const int*   ei    = (const int*)d_in[1];   // int64 downcast to int32 by harness
    const float* ew    = (const float*)d_in[2];
    const float* Wself = (const float*)d_in[3];
    const float* bself = (const float*)d_in[4];
    const float* Wnb   = (const float*)d_in[5];
    const float* bnb   = (const float*)d_in[6];
    const float* gamma = (const float*)d_in[7];
    const float* beta  = (const float*)d_in[8];
    float* out         = (float*)d_out;

    int N = in_sizes[0] / F;
    int E = in_sizes[2];

    int zt = N * (F / 4);
    k_zero<<<(zt + 255) / 256, 256>>>(N);

    long long tot = (long long)E * 32;
    int b1 = (int)((tot + 255) / 256);
    k_edge<<<b1, 256>>>(x, ei, ew, E, N);

    static const size_t smem = 196608;  // 192KB
    cudaFuncSetAttribute(k_fused, cudaFuncAttributeMaxDynamicSharedMemorySize, (int)smem);
    int b2 = (N + 127) / 128;
    k_fused<<<b2, 512, smem>>>(x, Wself, bself, Wnb, bnb, gamma, beta, out, N);
}

// round 7
// speedup vs baseline: 1.0614x; 1.0614x over previous
#include <cuda_runtime.h>

#define F 128
#define CAP_N 51200
#define CAP_E 650000

// Scratch (no cudaMalloc allowed). float4 type guarantees 16B alignment.
__device__ float4 g_agg4[(size_t)CAP_N * (F / 4)];  // raw weighted sums S
__device__ float  g_denom[CAP_N];                   // softmax denominators

// ---------------------------------------------------------------------------
// packed f32x2 helpers (Blackwell FFMA2 — PTX-only, 2x fp32 FMA throughput)
// ---------------------------------------------------------------------------
__device__ __forceinline__ void ffma2(unsigned long long& d,
                                      unsigned long long a,
                                      unsigned long long b) {
    asm("fma.rn.f32x2 %0, %1, %2, %0;" : "+l"(d) : "l"(a), "l"(b));
}
__device__ __forceinline__ float hadd2(unsigned long long v) {
    float lo, hi;
    asm("mov.b64 {%0, %1}, %2;" : "=f"(lo), "=f"(hi) : "l"(v));
    return lo + hi;
}

// ---------------------------------------------------------------------------
// K0: zero scratch (graph memset nodes can't target __device__ globals)
// ---------------------------------------------------------------------------
__global__ void k_zero(int N) {
    int i = blockIdx.x * blockDim.x + threadIdx.x;
    int total4 = N * (F / 4);
    if (i < total4)
        g_agg4[i] = make_float4(0.f, 0.f, 0.f, 0.f);
    if (i < N)
        g_denom[i] = 0.f;
}

// ---------------------------------------------------------------------------
// K1: merged edge pass (softmax div deferred — it cancels in the L2 norm):
//     denom[t] += exp(w[e]);  S[t][:] += exp(w[e]) * x[src][:]
// one warp per edge; expf computed ONCE per edge (lane 0) then shfl-broadcast.
// ---------------------------------------------------------------------------
__global__ void k_edge(const float* __restrict__ x,
                       const int* __restrict__ ei,
                       const float* __restrict__ w, int E, int N) {
    int gid = blockIdx.x * blockDim.x + threadIdx.x;
    int e = gid >> 5;
    int lane = gid & 31;
    if (e >= E) return;
    int s = ei[e];
    int t = ei[E + e];
    if ((unsigned)s >= (unsigned)N || (unsigned)t >= (unsigned)N) return;
    float ew = 0.f;
    if (lane == 0) {
        ew = expf(w[e]);
        atomicAdd(&g_denom[t], ew);
    }
    ew = __shfl_sync(0xffffffffu, ew, 0);
    float4 xv = reinterpret_cast<const float4*>(x)[(size_t)s * 32 + lane];
    float4 v = make_float4(ew * xv.x, ew * xv.y, ew * xv.z, ew * xv.w);
    atomicAdd(&g_agg4[(size_t)t * 32 + lane], v);
}

// ---------------------------------------------------------------------------
// K2 helper: one GEMM pass with k-paired FFMA2, rows + W both in smem.
// WS: k-paired W. One k2-row = 128 float2 = 64 ulonglong2 (stride 64).
// xr[i]: smem row pointers (ulonglong2 = 4 consecutive k as 2 k-pairs).
// acc[i][f]: f32x2 accumulators (even/odd k partial sums).
// ---------------------------------------------------------------------------
__device__ __forceinline__ void gemm_pass(const ulonglong2* __restrict__ WS,
                                          const ulonglong2* const* xr,
                                          unsigned long long (*acc)[4],
                                          int lane) {
    #pragma unroll 4
    for (int c = 0; c < 32; ++c) {          // chunk = 4 k = 2 k2 rows
        const ulonglong2* r0 = WS + (size_t)(2 * c) * 64;       // k2 = 2c
        const ulonglong2* r1 = WS + (size_t)(2 * c + 1) * 64;   // k2 = 2c+1
        ulonglong2 w0a = r0[2 * lane];
        ulonglong2 w0b = r0[2 * lane + 1];
        ulonglong2 w1a = r1[2 * lane];
        ulonglong2 w1b = r1[2 * lane + 1];
        #pragma unroll
        for (int i = 0; i < 4; ++i) {
            ulonglong2 xv = xr[i][c];       // broadcast LDS (N=1, free)
            ffma2(acc[i][0], xv.x, w0a.x);
            ffma2(acc[i][1], xv.x, w0a.y);
            ffma2(acc[i][2], xv.x, w0b.x);
            ffma2(acc[i][3], xv.x, w0b.y);
            ffma2(acc[i][0], xv.y, w1a.x);
            ffma2(acc[i][1], xv.y, w1a.y);
            ffma2(acc[i][2], xv.y, w1b.x);
            ffma2(acc[i][3], xv.y, w1b.y);
        }
    }
}

// ---------------------------------------------------------------------------
// K2: fused dual GEMM (FFMA2) -> deferred softmax-div+L2-norm -> proj-avg -> LN
// 512 threads (16 warps), 64 nodes/block, 4 rows/warp, 4 out-feats/lane.
// smem: WpS 64KB | WpN 64KB | Xs 32KB | As 32KB = 192KB.
// ---------------------------------------------------------------------------
__global__ __launch_bounds__(512, 1)
void k_fused(const float* __restrict__ x,
             const float* __restrict__ Wself, const float* __restrict__ bself,
             const float* __restrict__ Wnb, const float* __restrict__ bnb,
             const float* __restrict__ gamma, const float* __restrict__ beta,
             float* __restrict__ out, int N) {
    extern __shared__ float sm[];
    float* WpS = sm;            // [64 k2][128 f] float2 (k-paired W_self)
    float* WpN = sm + 16384;    // same for W_nb
    float* Xs  = sm + 32768;    // [64 rows][128] x
    float* As  = sm + 40960;    // [64 rows][128] raw agg S

    int tid = threadIdx.x;
    int base = blockIdx.x * 64;

    // stage W matrices into k-paired layout: Wp[k2][f] = (W[2k2][f], W[2k2+1][f])
    {
        const float4* gS = (const float4*)Wself;
        const float4* gN = (const float4*)Wnb;
        #pragma unroll
        for (int it = 0; it < 4; ++it) {
            int t4 = tid + it * 512;        // [0,2048)
            int k2 = t4 >> 5, g = t4 & 31;
            float4 a = gS[(2 * k2) * 32 + g];
            float4 b = gS[(2 * k2 + 1) * 32 + g];
            float2* d = (float2*)(WpS + k2 * 256) + g * 4;
            d[0] = make_float2(a.x, b.x);
            d[1] = make_float2(a.y, b.y);
            d[2] = make_float2(a.z, b.z);
            d[3] = make_float2(a.w, b.w);
            a = gN[(2 * k2) * 32 + g];
            b = gN[(2 * k2 + 1) * 32 + g];
            d = (float2*)(WpN + k2 * 256) + g * 4;
            d[0] = make_float2(a.x, b.x);
            d[1] = make_float2(a.y, b.y);
            d[2] = make_float2(a.z, b.z);
            d[3] = make_float2(a.w, b.w);
        }
    }
    // stage x / raw-agg rows for this block's 64 nodes (coalesced)
    {
        const float4* x4 = (const float4*)x;
        float4* sx = (float4*)Xs;
        float4* sa = (float4*)As;
        #pragma unroll
        for (int i = 0; i < 4; ++i) {
            int idx = tid + i * 512;        // < 2048
            int row = idx >> 5;
            int node = base + row;
            if (node < N) {
                sx[idx] = x4[(size_t)node * 32 + (idx & 31)];
                sa[idx] = g_agg4[(size_t)node * 32 + (idx & 31)];
            } else {
                sx[idx] = make_float4(0.f, 0.f, 0.f, 0.f);
                sa[idx] = make_float4(0.f, 0.f, 0.f, 0.f);
            }
        }
    }
    __syncthreads();

    int warp = tid >> 5, lane = tid & 31;
    int rbase = warp * 4;

    // smem row pointers
    const ulonglong2* xr[4];
    const ulonglong2* ar[4];
    #pragma unroll
    for (int i = 0; i < 4; ++i) {
        xr[i] = (const ulonglong2*)(Xs + (rbase + i) * 128);
        ar[i] = (const ulonglong2*)(As + (rbase + i) * 128);
    }

    unsigned long long acc[4][4];

    // ---- pass 1: self_feat = x @ W_self (kept in registers) ----
    #pragma unroll
    for (int i = 0; i < 4; ++i)
        #pragma unroll
        for (int f = 0; f < 4; ++f) acc[i][f] = 0ULL;
    gemm_pass((const ulonglong2*)WpS, xr, acc, lane);
    float4 sv[4];
    #pragma unroll
    for (int i = 0; i < 4; ++i) {
        sv[i].x = hadd2(acc[i][0]);
        sv[i].y = hadd2(acc[i][1]);
        sv[i].z = hadd2(acc[i][2]);
        sv[i].w = hadd2(acc[i][3]);
    }

    // ---- deferred normalization scalars: inv = 1/(||S|| + denom*1e-9) ----
    float inv4[4];
    #pragma unroll
    for (int i = 0; i < 4; ++i) {
        int node = base + rbase + i;
        float4 a = ((const float4*)As)[(rbase + i) * 32 + lane];
        float ss = a.x * a.x + a.y * a.y + a.z * a.z + a.w * a.w;
        #pragma unroll
        for (int off = 16; off; off >>= 1)
            ss += __shfl_xor_sync(0xffffffffu, ss, off);
        float dnm = (node < N) ? g_denom[node] : 1.f;
        inv4[i] = (ss > 0.f) ? 1.0f / (sqrtf(ss) + dnm * 1e-9f) : 0.f;
    }

    // ---- pass 2: nb_feat_raw = S @ W_nb ----
    #pragma unroll
    for (int i = 0; i < 4; ++i)
        #pragma unroll
        for (int f = 0; f < 4; ++f) acc[i][f] = 0ULL;
    gemm_pass((const ulonglong2*)WpN, ar, acc, lane);

    float4 bs = ((const float4*)bself)[lane];
    float4 bn = ((const float4*)bnb)[lane];
    float4 gm = ((const float4*)gamma)[lane];
    float4 bt = ((const float4*)beta)[lane];

    // ---- epilogue: combine -> proj-norm + LayerNorm -> store ----
    #pragma unroll
    for (int i = 0; i < 4; ++i) {
        int node = base + rbase + i;
        if (node >= N) continue;   // uniform per-warp tail
        float iv = inv4[i];
        float4 c;
        c.x = 0.5f * ((sv[i].x + bs.x) + (iv * hadd2(acc[i][0]) + bn.x));
        c.y = 0.5f * ((sv[i].y + bs.y) + (iv * hadd2(acc[i][1]) + bn.y));
        c.z = 0.5f * ((sv[i].z + bs.z) + (iv * hadd2(acc[i][2]) + bn.z));
        c.w = 0.5f * ((sv[i].w + bs.w) + (iv * hadd2(acc[i][3]) + bn.w));
        float s1 = c.x + c.y + c.z + c.w;
        float s2 = c.x * c.x + c.y * c.y + c.z * c.z + c.w * c.w;
        #pragma unroll
        for (int off = 16; off; off >>= 1) {
            s1 += __shfl_xor_sync(0xffffffffu, s1, off);
            s2 += __shfl_xor_sync(0xffffffffu, s2, off);
        }
        float d = sqrtf(s2) + 1e-9f;
        float invd = 1.0f / d;
        float mean = s1 * invd * (1.0f / 128.0f);
        float e2 = s2 * invd * invd * (1.0f / 128.0f);
        float var = e2 - mean * mean;
        float isd = rsqrtf(var + 1e-5f);
        float4 o;
        o.x = (c.x * invd - mean) * isd * gm.x + bt.x;
        o.y = (c.y * invd - mean) * isd * gm.y + bt.y;
        o.z = (c.z * invd - mean) * isd * gm.z + bt.z;
        o.w = (c.w * invd - mean) * isd * gm.w + bt.w;
        ((float4*)out)[(size_t)node * 32 + lane] = o;
    }
}

// ---------------------------------------------------------------------------
extern "C" void kernel_launch(void* const* d_in, const int* in_sizes, int n_in,
                              void* d_out, int out_size) {
    const float* x     = (const float*)d_in[0];
    const int*   ei    = (const int*)d_in[1];   // int64 downcast to int32 by harness
    const float* ew    = (const float*)d_in[2];
    const float* Wself = (const float*)d_in[3];
    const float* bself = (const float*)d_in[4];
    const float* Wnb   = (const float*)d_in[5];
    const float* bnb   = (const float*)d_in[6];
    const float* gamma = (const float*)d_in[7];
    const float* beta  = (const float*)d_in[8];
    float* out         = (float*)d_out;

    int N = in_sizes[0] / F;
    int E = in_sizes[2];

    int zt = N * (F / 4);
    k_zero<<<(zt + 255) / 256, 256>>>(N);

    long long tot = (long long)E * 32;
    int b1 = (int)((tot + 255) / 256);
    k_edge<<<b1, 256>>>(x, ei, ew, E, N);

    static const size_t smem = 196608;  // 192KB
    cudaFuncSetAttribute(k_fused, cudaFuncAttributeMaxDynamicSharedMemorySize, (int)smem);
    int b2 = (N + 63) / 64;
    k_fused<<<b2, 512, smem>>>(x, Wself, bself, Wnb, bnb, gamma, beta, out, N);
}

// round 8
// speedup vs baseline: 1.2989x; 1.2238x over previous
#include <cuda_runtime.h>

#define F 128
#define CAP_N 51200
#define CAP_E 650000

// Scratch (no cudaMalloc allowed). float4 type guarantees 16B alignment.
__device__ float4 g_agg4[(size_t)CAP_N * (F / 4)];  // raw weighted sums S
__device__ float  g_denom[CAP_N];                   // softmax denominators
__device__ float  g_ew[CAP_E];                      // exp(edge_weight)

// ---------------------------------------------------------------------------
// packed f32x2 helpers (Blackwell FFMA2 — PTX-only, 2x fp32 FMA throughput)
// ---------------------------------------------------------------------------
__device__ __forceinline__ void ffma2(unsigned long long& d,
                                      unsigned long long a,
                                      unsigned long long b) {
    asm("fma.rn.f32x2 %0, %1, %2, %0;" : "+l"(d) : "l"(a), "l"(b));
}
__device__ __forceinline__ float hadd2(unsigned long long v) {
    float lo, hi;
    asm("mov.b64 {%0, %1}, %2;" : "=f"(lo), "=f"(hi) : "l"(v));
    return lo + hi;
}

// ---------------------------------------------------------------------------
// K0: zero scratch
// ---------------------------------------------------------------------------
__global__ void k_zero(int N) {
    int i = blockIdx.x * blockDim.x + threadIdx.x;
    int total4 = N * (F / 4);
    if (i < total4)
        g_agg4[i] = make_float4(0.f, 0.f, 0.f, 0.f);
    if (i < N)
        g_denom[i] = 0.f;
}

// ---------------------------------------------------------------------------
// K1: ew[e] = exp(w[e]); denom[tgt] += ew[e]   (R4 version, measured fast)
// ---------------------------------------------------------------------------
__global__ void k_softmax_denom(const int* __restrict__ ei,
                                const float* __restrict__ w, int E, int N) {
    int e = blockIdx.x * blockDim.x + threadIdx.x;
    if (e >= E) return;
    int t = ei[E + e];
    float v = expf(w[e]);
    g_ew[e] = v;
    if ((unsigned)t < (unsigned)N)
        atomicAdd(&g_denom[t], v);
}

// ---------------------------------------------------------------------------
// K2: one warp per edge; agg[t] += (ew/denom) * x[src]  (R4 version)
// ---------------------------------------------------------------------------
__global__ void k_scatter(const float* __restrict__ x,
                          const int* __restrict__ ei, int E, int N) {
    int gid = blockIdx.x * blockDim.x + threadIdx.x;
    int e = gid >> 5;
    int lane = gid & 31;
    if (e >= E) return;
    int s = ei[e];
    int t = ei[E + e];
    if ((unsigned)s >= (unsigned)N || (unsigned)t >= (unsigned)N) return;
    float alpha = g_ew[e] / g_denom[t];
    float4 xv = reinterpret_cast<const float4*>(x)[(size_t)s * 32 + lane];
    float4 v = make_float4(alpha * xv.x, alpha * xv.y, alpha * xv.z, alpha * xv.w);
    atomicAdd(&g_agg4[(size_t)t * 32 + lane], v);
}

// ---------------------------------------------------------------------------
// K3 helper: GEMM pass, k-paired FFMA2, conflict-free W loads.
// WS row (one k2) = 128 float2 (per-feature k-pairs) = 64 ulonglong2.
// Lane loads u2[lane] (features 2L,2L+1) and u2[lane+32] (features 64+2L,65+2L)
// -> 16B-contiguous per warp -> conflict-free LDS.128.
// acc[i][0..3] = features 2L, 2L+1, 64+2L, 65+2L (as f32x2 even/odd-k halves).
// ---------------------------------------------------------------------------
__device__ __forceinline__ void gemm_pass(const ulonglong2* __restrict__ WS,
                                          const ulonglong2* const* xr,
                                          unsigned long long (*acc)[4],
                                          int lane) {
    #pragma unroll 4
    for (int c = 0; c < 32; ++c) {          // chunk = 4 k = 2 k2 rows
        const ulonglong2* r0 = WS + (size_t)(2 * c) * 64;       // k2 = 2c
        const ulonglong2* r1 = WS + (size_t)(2 * c + 1) * 64;   // k2 = 2c+1
        ulonglong2 w0a = r0[lane];
        ulonglong2 w0b = r0[lane + 32];
        ulonglong2 w1a = r1[lane];
        ulonglong2 w1b = r1[lane + 32];
        #pragma unroll
        for (int i = 0; i < 4; ++i) {
            ulonglong2 xv = xr[i][c];       // broadcast LDS (N=1, free)
            ffma2(acc[i][0], xv.x, w0a.x);
            ffma2(acc[i][1], xv.x, w0a.y);
            ffma2(acc[i][2], xv.x, w0b.x);
            ffma2(acc[i][3], xv.x, w0b.y);
            ffma2(acc[i][0], xv.y, w1a.x);
            ffma2(acc[i][1], xv.y, w1a.y);
            ffma2(acc[i][2], xv.y, w1b.x);
            ffma2(acc[i][3], xv.y, w1b.y);
        }
    }
}

// ---------------------------------------------------------------------------
// K3: fused dual GEMM (FFMA2) -> agg-L2norm -> proj-avg -> LayerNorm
// 512 threads (16 warps), 64 nodes/block, 4 rows/warp.
// Lane owns features {2L, 2L+1, 64+2L, 65+2L}.
// smem: WpS 64KB | WpN 64KB | Xs 32KB | As 32KB = 192KB.
// ---------------------------------------------------------------------------
__global__ __launch_bounds__(512, 1)
void k_fused(const float* __restrict__ x,
             const float* __restrict__ Wself, const float* __restrict__ bself,
             const float* __restrict__ Wnb, const float* __restrict__ bnb,
             const float* __restrict__ gamma, const float* __restrict__ beta,
             float* __restrict__ out, int N) {
    extern __shared__ float sm[];
    float* WpS = sm;            // [64 k2][128 f] float2 (k-paired W_self)
    float* WpN = sm + 16384;    // same for W_nb
    float* Xs  = sm + 32768;    // [64 rows][128] x
    float* As  = sm + 40960;    // [64 rows][128] raw agg S

    int tid = threadIdx.x;
    int base = blockIdx.x * 64;

    // stage W into k-paired layout: Wp[k2][f] = (W[2k2][f], W[2k2+1][f])
    {
        const float4* gS = (const float4*)Wself;
        const float4* gN = (const float4*)Wnb;
        #pragma unroll
        for (int it = 0; it < 4; ++it) {
            int t4 = tid + it * 512;        // [0,2048)
            int k2 = t4 >> 5, g = t4 & 31;
            float4 a = gS[(2 * k2) * 32 + g];
            float4 b = gS[(2 * k2 + 1) * 32 + g];
            float2* d = (float2*)(WpS + k2 * 256) + g * 4;
            d[0] = make_float2(a.x, b.x);
            d[1] = make_float2(a.y, b.y);
            d[2] = make_float2(a.z, b.z);
            d[3] = make_float2(a.w, b.w);
            a = gN[(2 * k2) * 32 + g];
            b = gN[(2 * k2 + 1) * 32 + g];
            d = (float2*)(WpN + k2 * 256) + g * 4;
            d[0] = make_float2(a.x, b.x);
            d[1] = make_float2(a.y, b.y);
            d[2] = make_float2(a.z, b.z);
            d[3] = make_float2(a.w, b.w);
        }
    }
    // stage x / raw-agg rows (coalesced)
    {
        const float4* x4 = (const float4*)x;
        float4* sx = (float4*)Xs;
        float4* sa = (float4*)As;
        #pragma unroll
        for (int i = 0; i < 4; ++i) {
            int idx = tid + i * 512;        // < 2048
            int row = idx >> 5;
            int node = base + row;
            if (node < N) {
                sx[idx] = x4[(size_t)node * 32 + (idx & 31)];
                sa[idx] = g_agg4[(size_t)node * 32 + (idx & 31)];
            } else {
                sx[idx] = make_float4(0.f, 0.f, 0.f, 0.f);
                sa[idx] = make_float4(0.f, 0.f, 0.f, 0.f);
            }
        }
    }
    __syncthreads();

    int warp = tid >> 5, lane = tid & 31;
    int rbase = warp * 4;

    const ulonglong2* xr[4];
    const ulonglong2* ar[4];
    #pragma unroll
    for (int i = 0; i < 4; ++i) {
        xr[i] = (const ulonglong2*)(Xs + (rbase + i) * 128);
        ar[i] = (const ulonglong2*)(As + (rbase + i) * 128);
    }

    unsigned long long acc[4][4];

    // ---- pass 1: self_feat = x @ W_self (kept in registers) ----
    #pragma unroll
    for (int i = 0; i < 4; ++i)
        #pragma unroll
        for (int f = 0; f < 4; ++f) acc[i][f] = 0ULL;
    gemm_pass((const ulonglong2*)WpS, xr, acc, lane);
    float4 sv[4];   // (f 2L, 2L+1, 64+2L, 65+2L)
    #pragma unroll
    for (int i = 0; i < 4; ++i) {
        sv[i].x = hadd2(acc[i][0]);
        sv[i].y = hadd2(acc[i][1]);
        sv[i].z = hadd2(acc[i][2]);
        sv[i].w = hadd2(acc[i][3]);
    }

    // ---- L2-norm scalars of agg: inv = 1/(||S|| + 1e-9); zero rows -> 0 ----
    float inv4[4];
    #pragma unroll
    for (int i = 0; i < 4; ++i) {
        float4 a = ((const float4*)As)[(rbase + i) * 32 + lane];
        float ss = a.x * a.x + a.y * a.y + a.z * a.z + a.w * a.w;
        #pragma unroll
        for (int off = 16; off; off >>= 1)
            ss += __shfl_xor_sync(0xffffffffu, ss, off);
        inv4[i] = 1.0f / (sqrtf(ss) + 1e-9f);
    }

    // ---- pass 2: nb_feat = (agg normalized, deferred) @ W_nb ----
    #pragma unroll
    for (int i = 0; i < 4; ++i)
        #pragma unroll
        for (int f = 0; f < 4; ++f) acc[i][f] = 0ULL;
    gemm_pass((const ulonglong2*)WpN, ar, acc, lane);

    // per-lane feature groups: float2 index lane and lane+32
    const float2* bs2 = (const float2*)bself;
    const float2* bn2 = (const float2*)bnb;
    const float2* gm2 = (const float2*)gamma;
    const float2* bt2 = (const float2*)beta;
    float2 bsA = bs2[lane], bsB = bs2[lane + 32];
    float2 bnA = bn2[lane], bnB = bn2[lane + 32];
    float2 gmA = gm2[lane], gmB = gm2[lane + 32];
    float2 btA = bt2[lane], btB = bt2[lane + 32];

    // ---- epilogue: combine -> proj-norm + LayerNorm -> store ----
    #pragma unroll
    for (int i = 0; i < 4; ++i) {
        int node = base + rbase + i;
        if (node >= N) continue;   // uniform per-warp tail
        float iv = inv4[i];
        float4 c;
        c.x = 0.5f * ((sv[i].x + bsA.x) + (iv * hadd2(acc[i][0]) + bnA.x));
        c.y = 0.5f * ((sv[i].y + bsA.y) + (iv * hadd2(acc[i][1]) + bnA.y));
        c.z = 0.5f * ((sv[i].z + bsB.x) + (iv * hadd2(acc[i][2]) + bnB.x));
        c.w = 0.5f * ((sv[i].w + bsB.y) + (iv * hadd2(acc[i][3]) + bnB.y));
        float s1 = c.x + c.y + c.z + c.w;
        float s2 = c.x * c.x + c.y * c.y + c.z * c.z + c.w * c.w;
        #pragma unroll
        for (int off = 16; off; off >>= 1) {
            s1 += __shfl_xor_sync(0xffffffffu, s1, off);
            s2 += __shfl_xor_sync(0xffffffffu, s2, off);
        }
        float d = sqrtf(s2) + 1e-9f;
        float invd = 1.0f / d;
        float mean = s1 * invd * (1.0f / 128.0f);
        float e2 = s2 * invd * invd * (1.0f / 128.0f);
        float var = e2 - mean * mean;
        float isd = rsqrtf(var + 1e-5f);
        float2 oA, oB;
        oA.x = (c.x * invd - mean) * isd * gmA.x + btA.x;
        oA.y = (c.y * invd - mean) * isd * gmA.y + btA.y;
        oB.x = (c.z * invd - mean) * isd * gmB.x + btB.x;
        oB.y = (c.w * invd - mean) * isd * gmB.y + btB.y;
        float2* o2 = (float2*)(out + (size_t)node * F);
        o2[lane] = oA;
        o2[lane + 32] = oB;
    }
}

// ---------------------------------------------------------------------------
extern "C" void kernel_launch(void* const* d_in, const int* in_sizes, int n_in,
                              void* d_out, int out_size) {
    const float* x     = (const float*)d_in[0];
    const int*   ei    = (const int*)d_in[1];   // int64 downcast to int32 by harness
    const float* ew    = (const float*)d_in[2];
    const float* Wself = (const float*)d_in[3];
    const float* bself = (const float*)d_in[4];
    const float* Wnb   = (const float*)d_in[5];
    const float* bnb   = (const float*)d_in[6];
    const float* gamma = (const float*)d_in[7];
    const float* beta  = (const float*)d_in[8];
    float* out         = (float*)d_out;

    int N = in_sizes[0] / F;
    int E = in_sizes[2];

    int zt = N * (F / 4);
    k_zero<<<(zt + 255) / 256, 256>>>(N);

    int b1 = (E + 255) / 256;
    k_softmax_denom<<<b1, 256>>>(ei, ew, E, N);

    long long tot = (long long)E * 32;
    int b2 = (int)((tot + 255) / 256);
    k_scatter<<<b2, 256>>>(x, ei, E, N);

    static const size_t smem = 196608;  // 192KB
    cudaFuncSetAttribute(k_fused, cudaFuncAttributeMaxDynamicSharedMemorySize, (int)smem);
    int b3 = (N + 63) / 64;
    k_fused<<<b3, 512, smem>>>(x, Wself, bself, Wnb, bnb, gamma, beta, out, N);
}

// round 9
// speedup vs baseline: 1.4650x; 1.1278x over previous
#include <cuda_runtime.h>
#include <cuda_bf16.h>

#define F 128
#define CAP_N 51200
#define CAP_E 650000

// Scratch (no cudaMalloc allowed)
__device__ float4 g_agg4[(size_t)CAP_N * (F / 4)];  // aggregated neighbor feats
__device__ float  g_denom[CAP_N];                   // softmax denominators
__device__ float  g_ew[CAP_E];                      // exp(edge_weight)

// ---------------------------------------------------------------------------
// K0: zero scratch
// ---------------------------------------------------------------------------
__global__ void k_zero(int N) {
    int i = blockIdx.x * blockDim.x + threadIdx.x;
    int total4 = N * (F / 4);
    if (i < total4)
        g_agg4[i] = make_float4(0.f, 0.f, 0.f, 0.f);
    if (i < N)
        g_denom[i] = 0.f;
}

// ---------------------------------------------------------------------------
// K1: ew[e] = exp(w[e]); denom[tgt] += ew[e]
// ---------------------------------------------------------------------------
__global__ void k_softmax_denom(const int* __restrict__ ei,
                                const float* __restrict__ w, int E, int N) {
    int e = blockIdx.x * blockDim.x + threadIdx.x;
    if (e >= E) return;
    int t = ei[E + e];
    float v = expf(w[e]);
    g_ew[e] = v;
    if ((unsigned)t < (unsigned)N)
        atomicAdd(&g_denom[t], v);
}

// ---------------------------------------------------------------------------
// K2: one warp per edge; agg[t] += (ew/denom) * x[src]
// ---------------------------------------------------------------------------
__global__ void k_scatter(const float* __restrict__ x,
                          const int* __restrict__ ei, int E, int N) {
    int gid = blockIdx.x * blockDim.x + threadIdx.x;
    int e = gid >> 5;
    int lane = gid & 31;
    if (e >= E) return;
    int s = ei[e];
    int t = ei[E + e];
    if ((unsigned)s >= (unsigned)N || (unsigned)t >= (unsigned)N) return;
    float alpha = g_ew[e] / g_denom[t];
    float4 xv = reinterpret_cast<const float4*>(x)[(size_t)s * 32 + lane];
    float4 v = make_float4(alpha * xv.x, alpha * xv.y, alpha * xv.z, alpha * xv.w);
    atomicAdd(&g_agg4[(size_t)t * 32 + lane], v);
}

// ---------------------------------------------------------------------------
// Tensor-core fused kernel
// ---------------------------------------------------------------------------
#define BLK_ROWS 128
#define KE 384          // extended K: [hi | lo | hi] x [hi | hi | lo]
#define RS 392          // padded bf16 row stride (784 B, conflict-free ldmatrix)
#define CSTRIDE 132     // padded f32 output row stride

__device__ __forceinline__ void mma16816(float* d,
                                         unsigned a0, unsigned a1,
                                         unsigned a2, unsigned a3,
                                         unsigned b0, unsigned b1) {
    asm volatile(
        "mma.sync.aligned.m16n8k16.row.col.f32.bf16.bf16.f32 "
        "{%0,%1,%2,%3}, {%4,%5,%6,%7}, {%8,%9}, {%0,%1,%2,%3};"
        : "+f"(d[0]), "+f"(d[1]), "+f"(d[2]), "+f"(d[3])
        : "r"(a0), "r"(a1), "r"(a2), "r"(a3), "r"(b0), "r"(b1));
}

__device__ __forceinline__ void ldsm4(unsigned& r0, unsigned& r1,
                                      unsigned& r2, unsigned& r3,
                                      unsigned addr) {
    asm volatile("ldmatrix.sync.aligned.m8n8.x4.shared.b16 {%0,%1,%2,%3}, [%4];"
                 : "=r"(r0), "=r"(r1), "=r"(r2), "=r"(r3) : "r"(addr));
}

// split f32 -> (hi, lo) bf16 and store into an extended-K row:
// row[k] = hi, row[128+k] = v1, row[256+k] = v2 (caller picks pattern)
__device__ __forceinline__ void split_store(__nv_bfloat16* row, int k, float v,
                                            bool a_pattern) {
    __nv_bfloat16 hi = __float2bfloat16(v);
    __nv_bfloat16 lo = __float2bfloat16(v - __bfloat162float(hi));
    row[k] = hi;
    if (a_pattern) {          // A' = [hi, lo, hi]
        row[128 + k] = lo;
        row[256 + k] = hi;
    } else {                  // W' = [hi, hi, lo]
        row[128 + k] = hi;
        row[256 + k] = lo;
    }
}

__global__ __launch_bounds__(512, 1)
void k_fused(const float* __restrict__ x,
             const float* __restrict__ Wself, const float* __restrict__ bself,
             const float* __restrict__ Wnb, const float* __restrict__ bnb,
             const float* __restrict__ gamma, const float* __restrict__ beta,
             float* __restrict__ out, int N) {
    extern __shared__ char smem[];
    __nv_bfloat16* Wb = (__nv_bfloat16*)smem;                // [128 n][392] 100352 B
    __nv_bfloat16* Ab = (__nv_bfloat16*)(smem + 100352);     // [128 m][392] 100352 B
    float* sb    = (float*)(smem + 200704);                  // bself   [128]
    float* snb   = (float*)(smem + 200704 + 512);            // bnb     [128]
    float* sg    = (float*)(smem + 200704 + 1024);           // gamma   [128]
    float* sbt   = (float*)(smem + 200704 + 1536);           // beta    [128]
    float* norms = (float*)(smem + 200704 + 2048);           // ||S||^2 [128]

    int tid = threadIdx.x;
    int wid = tid >> 5, lane = tid & 31;
    int base = blockIdx.x * BLK_ROWS;
    const float* aggf = (const float*)g_agg4;

    // ---- stage W_self^T (split) + x rows (split) + params + agg norms ----
    for (int idx = tid; idx < 16384; idx += 512) {
        int k = idx >> 7, n = idx & 127;
        split_store(Wb + n * RS, k, Wself[idx], false);
    }
    for (int idx = tid; idx < 16384; idx += 512) {
        int r = idx >> 7, c = idx & 127;
        int node = base + r; if (node >= N) node = N - 1;
        split_store(Ab + r * RS, c, x[(size_t)node * F + c], true);
    }
    if (tid < 128) {
        sb[tid] = bself[tid];
        snb[tid] = bnb[tid];
        sg[tid] = gamma[tid];
        sbt[tid] = beta[tid];
    }
    {   // agg row norms: warp wid handles rows wid*8 .. wid*8+7
        #pragma unroll
        for (int i = 0; i < 8; ++i) {
            int r = wid * 8 + i;
            int node = base + r; if (node >= N) node = N - 1;
            float4 a = g_agg4[(size_t)node * 32 + lane];
            float ss = a.x * a.x + a.y * a.y + a.z * a.z + a.w * a.w;
            #pragma unroll
            for (int off = 16; off; off >>= 1)
                ss += __shfl_xor_sync(0xffffffffu, ss, off);
            if (lane == 0) norms[r] = ss;
        }
    }
    __syncthreads();

    // ---- warp tiling: 16 warps = 8 M-groups x 2 N-halves ----
    int warp_m = wid >> 1, warp_n = wid & 1;
    int m0 = warp_m * 16;
    int q = lane >> 3, lr = lane & 7;

    unsigned a_base = (unsigned)__cvta_generic_to_shared(Ab);
    unsigned w_base = (unsigned)__cvta_generic_to_shared(Wb);

    // ldmatrix lane offsets (bf16 elements); ks adds 16 per step
    int a_off = (m0 + (q & 1) * 8 + lr) * RS + (q >> 1) * 8;
    int b_off[4];
    #pragma unroll
    for (int p = 0; p < 4; ++p)
        b_off[p] = (warp_n * 64 + p * 16 + (q >> 1) * 8 + lr) * RS + (q & 1) * 8;

    float accS[32], accN[32];
    #pragma unroll
    for (int i = 0; i < 32; ++i) { accS[i] = 0.f; accN[i] = 0.f; }

    // ---- pass 1: self = x' @ Wself'^T ----
    for (int ks = 0; ks < KE / 16; ++ks) {
        unsigned a0, a1, a2, a3;
        ldsm4(a0, a1, a2, a3, a_base + (unsigned)(a_off + ks * 16) * 2);
        #pragma unroll
        for (int p = 0; p < 4; ++p) {
            unsigned s0, s1, s2, s3;
            ldsm4(s0, s1, s2, s3, w_base + (unsigned)(b_off[p] + ks * 16) * 2);
            mma16816(&accS[(2 * p) * 4], a0, a1, a2, a3, s0, s1);
            mma16816(&accS[(2 * p + 1) * 4], a0, a1, a2, a3, s2, s3);
        }
    }
    __syncthreads();

    // ---- restage: W_nb^T (split) + raw agg rows (split) ----
    for (int idx = tid; idx < 16384; idx += 512) {
        int k = idx >> 7, n = idx & 127;
        split_store(Wb + n * RS, k, Wnb[idx], false);
    }
    for (int idx = tid; idx < 16384; idx += 512) {
        int r = idx >> 7, c = idx & 127;
        int node = base + r; if (node >= N) node = N - 1;
        split_store(Ab + r * RS, c, aggf[(size_t)node * F + c], true);
    }
    __syncthreads();

    // ---- pass 2: nb_raw = S' @ Wnb'^T ----
    for (int ks = 0; ks < KE / 16; ++ks) {
        unsigned a0, a1, a2, a3;
        ldsm4(a0, a1, a2, a3, a_base + (unsigned)(a_off + ks * 16) * 2);
        #pragma unroll
        for (int p = 0; p < 4; ++p) {
            unsigned s0, s1, s2, s3;
            ldsm4(s0, s1, s2, s3, w_base + (unsigned)(b_off[p] + ks * 16) * 2);
            mma16816(&accN[(2 * p) * 4], a0, a1, a2, a3, s0, s1);
            mma16816(&accN[(2 * p + 1) * 4], a0, a1, a2, a3, s2, s3);
        }
    }
    __syncthreads();

    // ---- combine into Cbuf (reuse Ab as f32 [128][CSTRIDE]) ----
    float* Cb = (float*)Ab;
    {
        int row0 = m0 + (lane >> 2);
        int row1 = row0 + 8;
        float inv0 = 1.f / (sqrtf(norms[row0]) + 1e-9f);
        float inv1 = 1.f / (sqrtf(norms[row1]) + 1e-9f);
        int tr = lane & 3;
        #pragma unroll
        for (int nt = 0; nt < 8; ++nt) {
            int col = warp_n * 64 + nt * 8 + 2 * tr;
            float bs0 = sb[col], bs1 = sb[col + 1];
            float bn0 = snb[col], bn1 = snb[col + 1];
            const float* dS = &accS[nt * 4];
            const float* dN = &accN[nt * 4];
            float2 c0, c1;
            c0.x = 0.5f * ((dS[0] + bs0) + (inv0 * dN[0] + bn0));
            c0.y = 0.5f * ((dS[1] + bs1) + (inv0 * dN[1] + bn1));
            c1.x = 0.5f * ((dS[2] + bs0) + (inv1 * dN[2] + bn0));
            c1.y = 0.5f * ((dS[3] + bs1) + (inv1 * dN[3] + bn1));
            *(float2*)(Cb + row0 * CSTRIDE + col) = c0;
            *(float2*)(Cb + row1 * CSTRIDE + col) = c1;
        }
    }
    __syncthreads();

    // ---- final: projective normalize + LayerNorm, write out ----
    float4 gm = ((const float4*)sg)[lane];
    float4 bt4 = ((const float4*)sbt)[lane];
    #pragma unroll
    for (int i = 0; i < 8; ++i) {
        int r = wid * 8 + i;
        int node = base + r;
        if (node >= N) continue;   // uniform per warp
        float4 c = *(const float4*)(Cb + r * CSTRIDE + lane * 4);
        float s1 = c.x + c.y + c.z + c.w;
        float s2 = c.x * c.x + c.y * c.y + c.z * c.z + c.w * c.w;
        #pragma unroll
        for (int off = 16; off; off >>= 1) {
            s1 += __shfl_xor_sync(0xffffffffu, s1, off);
            s2 += __shfl_xor_sync(0xffffffffu, s2, off);
        }
        float d = sqrtf(s2) + 1e-9f;
        float invd = 1.0f / d;
        float mean = s1 * invd * (1.0f / 128.0f);
        float e2 = s2 * invd * invd * (1.0f / 128.0f);
        float var = e2 - mean * mean;
        float isd = rsqrtf(var + 1e-5f);
        float4 o;
        o.x = (c.x * invd - mean) * isd * gm.x + bt4.x;
        o.y = (c.y * invd - mean) * isd * gm.y + bt4.y;
        o.z = (c.z * invd - mean) * isd * gm.z + bt4.z;
        o.w = (c.w * invd - mean) * isd * gm.w + bt4.w;
        ((float4*)out)[(size_t)node * 32 + lane] = o;
    }
}

// ---------------------------------------------------------------------------
extern "C" void kernel_launch(void* const* d_in, const int* in_sizes, int n_in,
                              void* d_out, int out_size) {
    const float* x     = (const float*)d_in[0];
    const int*   ei    = (const int*)d_in[1];   // int64 downcast to int32 by harness
    const float* ew    = (const float*)d_in[2];
    const float* Wself = (const float*)d_in[3];
    const float* bself = (const float*)d_in[4];
    const float* Wnb   = (const float*)d_in[5];
    const float* bnb   = (const float*)d_in[6];
    const float* gamma = (const float*)d_in[7];
    const float* beta  = (const float*)d_in[8];
    float* out         = (float*)d_out;

    int N = in_sizes[0] / F;
    int E = in_sizes[2];

    int zt = N * (F / 4);
    k_zero<<<(zt + 255) / 256, 256>>>(N);

    int b1 = (E + 255) / 256;
    k_softmax_denom<<<b1, 256>>>(ei, ew, E, N);

    long long tot = (long long)E * 32;
    int b2 = (int)((tot + 255) / 256);
    k_scatter<<<b2, 256>>>(x, ei, E, N);

    static const size_t smem = 203264;
    cudaFuncSetAttribute(k_fused, cudaFuncAttributeMaxDynamicSharedMemorySize, (int)smem);
    int b3 = (N + BLK_ROWS - 1) / BLK_ROWS;
    k_fused<<<b3, 512, smem>>>(x, Wself, bself, Wnb, bnb, gamma, beta, out, N);
}